// round 8
// baseline (speedup 1.0000x reference)
#include <cuda_runtime.h>
#include <cuda_fp16.h>
#include <math.h>
#include <stdint.h>

#define BSZ   512
#define LEN   100
#define NCAND 64
#define DIM   256
#define KIN   32

typedef unsigned long long u64;

// Scratch (no allocations allowed)
__device__ float  g_inter[BSZ * KIN * DIM];
__device__ float  g_scores[BSZ * KIN * LEN];        // [b][k][l]
__device__ __half g_i1[BSZ * KIN * DIM];            // interest splits
__device__ __half g_i2[BSZ * KIN * DIM];
__device__ __half g_h1[256 * 256];                  // W splits
__device__ __half g_h2[256 * 256];
__device__ __half g_c1[KIN * 256];                  // codes splits
__device__ __half g_c2[KIN * 256];

// ---- packed fp32x2 helpers --------------------------------------------------
__device__ __forceinline__ u64 ffma2(u64 a, u64 b, u64 c) {
    u64 d;
    asm("fma.rn.f32x2 %0, %1, %2, %3;" : "=l"(d) : "l"(a), "l"(b), "l"(c));
    return d;
}
__device__ __forceinline__ u64 pack2(float lo, float hi) {
    u64 r;
    asm("mov.b64 %0, {%1, %2};" : "=l"(r) : "f"(lo), "f"(hi));
    return r;
}
__device__ __forceinline__ u64 packu(uint32_t a, uint32_t b) {
    u64 r;
    asm("mov.b64 %0, {%1, %2};" : "=l"(r) : "r"(a), "r"(b));
    return r;
}
__device__ __forceinline__ float2 unpack2(u64 v) {
    float2 r;
    asm("mov.b64 {%0, %1}, %2;" : "=f"(r.x), "=f"(r.y) : "l"(v));
    return r;
}

// ---- mma.sync helpers ---------------------------------------------------------
__device__ __forceinline__ uint32_t smem_u32(const void* p) {
    uint32_t a;
    asm("{ .reg .u64 t; cvta.to.shared.u64 t, %1; cvt.u32.u64 %0, t; }" : "=r"(a) : "l"(p));
    return a;
}
__device__ __forceinline__ void ldsm4(uint32_t* r, uint32_t addr) {
    asm volatile("ldmatrix.sync.aligned.m8n8.x4.shared.b16 {%0,%1,%2,%3}, [%4];"
                 : "=r"(r[0]), "=r"(r[1]), "=r"(r[2]), "=r"(r[3]) : "r"(addr) : "memory");
}
__device__ __forceinline__ void ldsm4t(uint32_t* r, uint32_t addr) {
    asm volatile("ldmatrix.sync.aligned.m8n8.x4.trans.shared.b16 {%0,%1,%2,%3}, [%4];"
                 : "=r"(r[0]), "=r"(r[1]), "=r"(r[2]), "=r"(r[3]) : "r"(addr) : "memory");
}
__device__ __forceinline__ void mma16816(float* d, const uint32_t* a, uint32_t b0, uint32_t b1) {
    asm volatile("mma.sync.aligned.m16n8k16.row.col.f32.f16.f16.f32 "
                 "{%0,%1,%2,%3}, {%4,%5,%6,%7}, {%8,%9}, {%0,%1,%2,%3};"
                 : "+f"(d[0]), "+f"(d[1]), "+f"(d[2]), "+f"(d[3])
                 : "r"(a[0]), "r"(a[1]), "r"(a[2]), "r"(a[3]), "r"(b0), "r"(b1));
}

#define SWZ(o) ((o) ^ (((o) >> 3) & 0x70))

__device__ __forceinline__ uint32_t h2_u32(__half a, __half b) {
    __half2 t(a, b);
    return *reinterpret_cast<uint32_t*>(&t);
}
__device__ __forceinline__ void split_pack(float x, float y, uint32_t& lo, uint32_t& hi) {
    const __half ax = __float2half_rn(x), ay = __float2half_rn(y);
    const __half bx = __float2half_rn(x - __half2float(ax));
    const __half by = __float2half_rn(y - __half2float(ay));
    lo = h2_u32(ax, ay);
    hi = h2_u32(bx, by);
}

// ---------------------------------------------------------------------------
// splits: W and codes -> fp16 2-level
// ---------------------------------------------------------------------------
__global__ void kw_split(const float* __restrict__ W) {
    const int i = blockIdx.x * 256 + threadIdx.x;
    const float a = W[i];
    const __half h1 = __float2half_rn(a);
    g_h1[i] = h1;
    g_h2[i] = __float2half_rn(a - __half2float(h1));
}
__global__ void kc_split(const float* __restrict__ codes) {
    const int i = blockIdx.x * 256 + threadIdx.x;
    const float a = codes[i];
    const __half h1 = __float2half_rn(a);
    g_c1[i] = h1;
    g_c2[i] = __float2half_rn(a - __half2float(h1));
}

// ---------------------------------------------------------------------------
// K1F: fused  proj = tanh(hist @ W^T)  ->  scores = proj @ codes^T.
// One CTA per 128 M-rows. Proj never touches DRAM.
// SMEM: GA(32K hist splits) | GB(32K W splits) | CD(16K codes splits) | SCORE(16K)
// PART (score partials, 64K) aliases GA+GB between GEMM phases.
// ---------------------------------------------------------------------------
#define GA_OFF 0
#define GB_OFF 32768
#define CD_OFF 65536
#define SC_OFF 81920
#define K1_DYN (98304 + 1024)

__global__ void __launch_bounds__(256, 2) k1f(const float* __restrict__ hist) {
    extern __shared__ char smem_raw[];
    const int tid = threadIdx.x;
    const int wid = tid >> 5;
    const int lane = tid & 31;
    const int warp_m = wid >> 2;
    const int warp_n = wid & 3;
    const int m0 = blockIdx.x * 128;
    const int g  = lane >> 3;
    const int rw = lane & 7;
    const int gid = lane >> 2, tig = lane & 3;

    const uint32_t sb_raw = smem_u32(smem_raw);
    const uint32_t sb = (sb_raw + 1023u) & ~1023u;
    char* smem = smem_raw + (sb - sb_raw);
    float* SCORE = (float*)(smem + SC_OFF);

    for (int i = tid; i < 4096; i += 256) SCORE[i] = 0.f;

    for (int half = 0; half < 2; half++) {
        const int n0 = half * 128;

        // ---- codes splits for this half into CD
#pragma unroll
        for (int t = 0; t < 4; t++) {
            const int idx = tid + t * 256;          // 0..1023
            const int lvl = idx >> 9;
            const int j = idx & 511;
            const int r = j >> 4, u = j & 15;
            const int c = u * 8;
            const int p = c >> 6, cl = c & 63;
            const __half* srcp = lvl ? g_c2 : g_c1;
            const uint4 v = *(const uint4*)&srcp[(size_t)r * 256 + n0 + c];
            *(uint4*)(smem + CD_OFF + lvl * 8192 + p * 4096 + SWZ((uint32_t)(r * 128 + cl * 2))) = v;
        }

        // ---- proj GEMM (3-pass fp16 split), acc = tile [128 m][128 c]
        float acc[4][4][4];
#pragma unroll
        for (int mt = 0; mt < 4; mt++)
#pragma unroll
            for (int nt = 0; nt < 4; nt++)
#pragma unroll
                for (int i = 0; i < 4; i++) acc[mt][nt][i] = 0.f;

        for (int kc = 0; kc < 4; kc++) {
#pragma unroll
            for (int t = 0; t < 8; t++) {
                const int idx = tid + t * 256;
                const int r = idx >> 4, c4 = idx & 15;
                const float4 a = __ldg((const float4*)&hist[(size_t)(m0 + r) * 256 + kc * 64 + c4 * 4]);
                uint32_t l0x, h0x, l0y, h0y;
                split_pack(a.x, a.y, l0x, h0x);
                split_pack(a.z, a.w, l0y, h0y);
                const uint32_t off = SWZ((uint32_t)(r * 128 + c4 * 8));
                *(uint2*)(smem + GA_OFF + off)         = make_uint2(l0x, l0y);
                *(uint2*)(smem + GA_OFF + 16384 + off) = make_uint2(h0x, h0y);
            }
            {
                const __half* gw[2] = {g_h1, g_h2};
#pragma unroll
                for (int lv = 0; lv < 2; lv++) {
#pragma unroll
                    for (int t = 0; t < 4; t++) {
                        const int idx = tid + t * 256;
                        const int n = idx >> 3, u = idx & 7;
                        const uint4 v = *(const uint4*)&gw[lv][(size_t)(n0 + n) * 256 + kc * 64 + u * 8];
                        *(uint4*)(smem + GB_OFF + lv * 16384 + SWZ((uint32_t)(n * 128 + u * 16))) = v;
                    }
                }
            }
            __syncthreads();

#pragma unroll
            for (int ks = 0; ks < 4; ks++) {
                const int k0 = ks * 16;
                uint32_t aoff[4], boff[2];
#pragma unroll
                for (int mt = 0; mt < 4; mt++) {
                    const int row = warp_m * 64 + mt * 16 + ((g & 1) << 3) + rw;
                    const int kk  = k0 + ((g >> 1) << 3);
                    aoff[mt] = sb + GA_OFF + SWZ((uint32_t)(row * 128 + kk * 2));
                }
#pragma unroll
                for (int nt2 = 0; nt2 < 2; nt2++) {
                    const int row = warp_n * 32 + nt2 * 16 + ((g >> 1) << 3) + rw;
                    const int kk  = k0 + ((g & 1) << 3);
                    boff[nt2] = sb + GB_OFF + SWZ((uint32_t)(row * 128 + kk * 2));
                }
                uint32_t a0[4][4], a1[4][4], b0[2][4], b1[2][4];
#pragma unroll
                for (int mt = 0; mt < 4; mt++) { ldsm4(a0[mt], aoff[mt]); ldsm4(a1[mt], aoff[mt] + 16384); }
#pragma unroll
                for (int nt2 = 0; nt2 < 2; nt2++) { ldsm4(b0[nt2], boff[nt2]); ldsm4(b1[nt2], boff[nt2] + 16384); }
#pragma unroll
                for (int mt = 0; mt < 4; mt++)
#pragma unroll
                    for (int nt = 0; nt < 4; nt++) {
                        const int h = nt >> 1, q = (nt & 1) * 2;
                        mma16816(acc[mt][nt], a0[mt], b0[h][q], b0[h][q + 1]);
                        mma16816(acc[mt][nt], a0[mt], b1[h][q], b1[h][q + 1]);
                        mma16816(acc[mt][nt], a1[mt], b0[h][q], b0[h][q + 1]);
                    }
            }
            __syncthreads();
        }

        // ---- tanh in registers
#pragma unroll
        for (int mt = 0; mt < 4; mt++)
#pragma unroll
            for (int nt = 0; nt < 4; nt++)
#pragma unroll
                for (int i = 0; i < 4; i++) acc[mt][nt][i] = tanhf(acc[mt][nt][i]);

        // ---- scores GEMM: A = acc (register-direct, split), B = codes splits.
        float* PART = (float*)(smem + wid * 8192);
#pragma unroll
        for (int mt = 0; mt < 4; mt++) {
            float sp[4][4];
#pragma unroll
            for (int nt8 = 0; nt8 < 4; nt8++)
#pragma unroll
                for (int i = 0; i < 4; i++) sp[nt8][i] = 0.f;

#pragma unroll
            for (int ks = 0; ks < 2; ks++) {
                uint32_t A1[4], A2[4];
                split_pack(acc[mt][ks * 2][0], acc[mt][ks * 2][1], A1[0], A2[0]);
                split_pack(acc[mt][ks * 2][2], acc[mt][ks * 2][3], A1[1], A2[1]);
                split_pack(acc[mt][ks * 2 + 1][0], acc[mt][ks * 2 + 1][1], A1[2], A2[2]);
                split_pack(acc[mt][ks * 2 + 1][2], acc[mt][ks * 2 + 1][3], A1[3], A2[3]);

                const int koff = warp_n * 32 + ks * 16;
                const int p = koff >> 6, kl = koff & 63;
                uint32_t B1[2][4], B2[2][4];
#pragma unroll
                for (int nt2 = 0; nt2 < 2; nt2++) {
                    const int row = nt2 * 16 + ((g >> 1) << 3) + rw;
                    const uint32_t off = sb + CD_OFF + p * 4096 +
                                         SWZ((uint32_t)(row * 128 + (kl + ((g & 1) << 3)) * 2));
                    ldsm4(B1[nt2], off);
                    ldsm4(B2[nt2], off + 8192);
                }
#pragma unroll
                for (int nt8 = 0; nt8 < 4; nt8++) {
                    const int h = nt8 >> 1, q = (nt8 & 1) * 2;
                    mma16816(sp[nt8], A1, B1[h][q], B1[h][q + 1]);
                    mma16816(sp[nt8], A1, B2[h][q], B2[h][q + 1]);
                    mma16816(sp[nt8], A2, B1[h][q], B1[h][q + 1]);
                    mma16816(sp[nt8], A2, B2[h][q], B2[h][q + 1]);
                }
            }
#pragma unroll
            for (int nt8 = 0; nt8 < 4; nt8++) {
                const int n = nt8 * 8 + tig * 2;
                PART[(mt * 16 + gid) * 32 + n]         = sp[nt8][0];
                PART[(mt * 16 + gid) * 32 + n + 1]     = sp[nt8][1];
                PART[(mt * 16 + gid + 8) * 32 + n]     = sp[nt8][2];
                PART[(mt * 16 + gid + 8) * 32 + n + 1] = sp[nt8][3];
            }
        }
        __syncthreads();

        // ---- reduce partials over warp_n into SCORE
        {
            const float* PA = (const float*)smem;
            for (int idx = tid; idx < 4096; idx += 256) {
                const int r = idx >> 5, n = idx & 31;
                const int wm = r >> 6, rl = r & 63;
                const int base = (wm * 4) * 2048 + rl * 32 + n;
                SCORE[idx] += PA[base] + PA[base + 2048] + PA[base + 4096] + PA[base + 6144];
            }
        }
        __syncthreads();
    }

    // ---- write scores to g_scores[b][k][l]
    for (int idx = tid; idx < 4096; idx += 256) {
        const int r = idx >> 5, n = idx & 31;
        const int M = m0 + r;
        const int b = M / 100, l = M - b * 100;
        g_scores[(size_t)b * 3200 + n * 100 + l] = SCORE[idx];
    }
}

// ---------------------------------------------------------------------------
// K2F: per-batch fused  softmax(scores) -> interests = attn @ hist (4-pass).
// ---------------------------------------------------------------------------
__global__ void __launch_bounds__(128) k2f(const float* __restrict__ hist,
                                           const int* __restrict__ numInt) {
    __shared__ __align__(16) char Asm[16384];
    __shared__ __align__(16) char Bsm[32768];

    const int b = blockIdx.x;
    const int tid = threadIdx.x;
    const int w = tid >> 5;
    const int lane = tid & 31;
    const int g = lane >> 3, rw = lane & 7;
    const uint32_t sbA = smem_u32(Asm);
    const uint32_t sbB = smem_u32(Bsm);

    // ---- softmax (sc overlays Bsm, which is unused until the chunk loop)
    float* sc = (float*)Bsm;   // [32][100] flat
    {
        const float* src = g_scores + (size_t)b * 3200;
        for (int idx = tid; idx < 3200; idx += 128) sc[idx] = src[idx];
    }
    __syncthreads();
    {
        const int ni = numInt[b];
        for (int k = w; k < 32; k += 4) {
            if (k >= ni) {
                for (int l = lane; l < LEN; l += 32) sc[k * 100 + l] = 0.01f;
            } else {
                float m = -3.4e38f;
                for (int l = lane; l < LEN; l += 32) m = fmaxf(m, sc[k * 100 + l]);
#pragma unroll
                for (int off = 16; off; off >>= 1)
                    m = fmaxf(m, __shfl_xor_sync(0xffffffffu, m, off));
                float s = 0.f;
                for (int l = lane; l < LEN; l += 32) {
                    float e = expf(sc[k * 100 + l] - m);
                    sc[k * 100 + l] = e;
                    s += e;
                }
#pragma unroll
                for (int off = 16; off; off >>= 1) s += __shfl_xor_sync(0xffffffffu, s, off);
                for (int l = lane; l < LEN; l += 32) sc[k * 100 + l] = sc[k * 100 + l] / s;
            }
        }
    }
    __syncthreads();

    // ---- write attn fp16 splits directly into swizzled Asm, pad L to 128
    for (int idx = tid; idx < 2048; idx += 128) {
        const int k = idx >> 6;
        const int l2 = (idx & 63) * 2;
        const float v0 = (l2 < 100) ? sc[k * 100 + l2] : 0.f;
        const float v1 = (l2 + 1 < 100) ? sc[k * 100 + l2 + 1] : 0.f;
        uint32_t lo, hi;
        split_pack(v0, v1, lo, hi);
        const int h = l2 >> 6, ll = l2 & 63;
        const uint32_t off = SWZ((uint32_t)((h * 32 + k) * 128 + ll * 2));
        *(uint32_t*)(Asm + off)        = lo;
        *(uint32_t*)(Asm + 8192 + off) = hi;
    }
    __syncthreads();

    float acc[2][8][4];
#pragma unroll
    for (int mt = 0; mt < 2; mt++)
#pragma unroll
        for (int nt = 0; nt < 8; nt++)
#pragma unroll
            for (int i = 0; i < 4; i++) acc[mt][nt][i] = 0.f;

    const float* Hb = hist + (size_t)b * LEN * DIM;

    for (int ch = 0; ch < 4; ch++) {
        const int l0 = ch * 32;
#pragma unroll
        for (int t = 0; t < 16; t++) {
            const int idx = tid + t * 128;
            const int lr = idx >> 6, c4 = idx & 63;
            const int l = l0 + lr;
            float4 a = make_float4(0.f, 0.f, 0.f, 0.f);
            if (l < LEN) a = __ldg((const float4*)&Hb[(size_t)l * 256 + c4 * 4]);
            uint32_t lx, hx, ly, hy;
            split_pack(a.x, a.y, lx, hx);
            split_pack(a.z, a.w, ly, hy);
            const int d = c4 * 4;
            const int p = d >> 6, dcol = d & 63;
            const uint32_t off = p * 4096 + SWZ((uint32_t)(lr * 128 + dcol * 2));
            *(uint2*)(Bsm + off)         = make_uint2(lx, ly);
            *(uint2*)(Bsm + 16384 + off) = make_uint2(hx, hy);
        }
        __syncthreads();

#pragma unroll
        for (int ks2 = 0; ks2 < 2; ks2++) {
            const int kk = l0 + ks2 * 16;
            const int half = kk >> 6, lloc = kk & 63;

            uint32_t a0[2][4], a1[2][4];
#pragma unroll
            for (int mt = 0; mt < 2; mt++) {
                const int row = mt * 16 + ((g & 1) << 3) + rw;
                const uint32_t ao = SWZ((uint32_t)((half * 32 + row) * 128 + (lloc + ((g >> 1) << 3)) * 2));
                ldsm4(a0[mt], sbA + ao);
                ldsm4(a1[mt], sbA + 8192 + ao);
            }

            const int trow = ks2 * 16 + (lane & 7) + ((lane >> 3) & 1) * 8;
            const int tcolb = ((lane >> 4) & 1) * 8;
#pragma unroll
            for (int ntt = 0; ntt < 4; ntt++) {
                const uint32_t bo = w * 4096 + SWZ((uint32_t)(trow * 128 + (ntt * 16 + tcolb) * 2));
                uint32_t bl0[4], bl1[4];
                ldsm4t(bl0, sbB + bo);
                ldsm4t(bl1, sbB + 16384 + bo);
#pragma unroll
                for (int mt = 0; mt < 2; mt++) {
                    float* c0 = acc[mt][ntt * 2];
                    float* c1 = acc[mt][ntt * 2 + 1];
                    mma16816(c0, a0[mt], bl0[0], bl0[1]);
                    mma16816(c0, a0[mt], bl1[0], bl1[1]);
                    mma16816(c0, a1[mt], bl0[0], bl0[1]);
                    mma16816(c0, a1[mt], bl1[0], bl1[1]);
                    mma16816(c1, a0[mt], bl0[2], bl0[3]);
                    mma16816(c1, a0[mt], bl1[2], bl1[3]);
                    mma16816(c1, a1[mt], bl0[2], bl0[3]);
                    mma16816(c1, a1[mt], bl1[2], bl1[3]);
                }
            }
        }
        __syncthreads();
    }

    // epilogue: fp32 interests + fp16 splits
    const int gid = lane >> 2, tig = lane & 3;
    float* Ib = g_inter + (size_t)b * KIN * DIM;
    __half* I1 = g_i1 + (size_t)b * KIN * DIM;
    __half* I2 = g_i2 + (size_t)b * KIN * DIM;
#pragma unroll
    for (int mt = 0; mt < 2; mt++) {
#pragma unroll
        for (int nt = 0; nt < 8; nt++) {
            const int k = mt * 16 + gid;
            const int d = w * 64 + nt * 8 + tig * 2;
#pragma unroll
            for (int hh = 0; hh < 2; hh++) {
                const int kk = k + hh * 8;
                const float vx = acc[mt][nt][hh * 2], vy = acc[mt][nt][hh * 2 + 1];
                *(float2*)&Ib[(size_t)kk * 256 + d] = make_float2(vx, vy);
                uint32_t lo, hi;
                split_pack(vx, vy, lo, hi);
                *(uint32_t*)&I1[(size_t)kk * 256 + d] = lo;
                *(uint32_t*)&I2[(size_t)kk * 256 + d] = hi;
            }
        }
    }
}

// ---------------------------------------------------------------------------
// K4: 2 blocks/batch. w-GEMM + rank exact fp32; user-GEMM via fp16-split mma.
// ---------------------------------------------------------------------------
#define K4_SMEM (62464 + 1024)

__global__ __launch_bounds__(256) void k4_kernel(const float* __restrict__ cand,
                                                 const int* __restrict__ catCnt,
                                                 float* __restrict__ out) {
    extern __shared__ char k4raw[];
    const int b = blockIdx.x >> 1;
    const int nbase = (blockIdx.x & 1) * 32;
    const int tid = threadIdx.x;
    const int w = tid >> 5;
    const int lane = tid & 31;

    const uint32_t sbr = smem_u32(k4raw);
    const uint32_t sb = (sbr + 1023u) & ~1023u;
    char* s = k4raw + (sb - sbr);
    float* row_sm  = (float*)(s);
    float* partial = (float*)(s + 8192);
    float* wfull   = (float*)(s + 16384);
    float* wmaskT  = (float*)(s + 17408);
    char*  ism     = s + 21504;
    char*  wmsm    = s + 54272;
    const uint32_t u_ism  = sb + 21504;
    const uint32_t u_wmsm = sb + 54272;

    {
        const uint4* s1 = (const uint4*)(g_i1 + (size_t)b * 8192);
        const uint4* s2 = (const uint4*)(g_i2 + (size_t)b * 8192);
#pragma unroll
        for (int t = 0; t < 4; t++) {
            const int idx = tid + t * 256;
            const int k = idx >> 5, c8 = idx & 31;
            const int d = c8 * 8, p = d >> 6, dloc = d & 63;
            const uint32_t off = p * 4096 + SWZ((uint32_t)(k * 128 + dloc * 2));
            *(uint4*)(ism + off)         = s1[idx];
            *(uint4*)(ism + 16384 + off) = s2[idx];
        }
    }

    u64 ireg2[16];
    {
        const u64* ibase = (const u64*)(g_inter + (size_t)b * 8192 + (size_t)lane * 256 + w * 32);
#pragma unroll
        for (int j = 0; j < 16; j++) ireg2[j] = ibase[j];
    }

    const int cc = catCnt[b];
    int dynK = (int)ceilf(log2f(8.0f * (float)cc));
    dynK = dynK < 1 ? 1 : (dynK > 32 ? 32 : dynK);

    const float* Cb = cand + (size_t)b * NCAND * DIM + (size_t)nbase * DIM;
    for (int n0 = 0; n0 < 32; n0 += 8) {
        const float4* src = (const float4*)(Cb + (size_t)n0 * DIM);
        float4* dst = (float4*)row_sm;
        dst[tid] = src[tid];
        dst[tid + 256] = src[tid + 256];
        __syncthreads();

        u64 p[8];
#pragma unroll
        for (int r = 0; r < 8; r++) p[r] = 0ull;
        const uint4* rbase4 = (const uint4*)row_sm;
#pragma unroll
        for (int j4 = 0; j4 < 8; j4++) {
            const u64 iv0 = ireg2[j4 * 2], iv1 = ireg2[j4 * 2 + 1];
            const int coff = w * 8 + j4;
#pragma unroll
            for (int r = 0; r < 8; r++) {
                const uint4 v = rbase4[r * 64 + coff];
                p[r] = ffma2(iv0, packu(v.x, v.y), p[r]);
                p[r] = ffma2(iv1, packu(v.z, v.w), p[r]);
            }
        }
#pragma unroll
        for (int r = 0; r < 8; r++) {
            float2 t = unpack2(p[r]);
            partial[w * 256 + r * 32 + lane] = t.x + t.y;
        }
        __syncthreads();

        {
            const int k = tid & 31, r = tid >> 5;
            float ssum = 0.f;
#pragma unroll
            for (int ww = 0; ww < 8; ww++) ssum += partial[ww * 256 + r * 32 + k];
            wfull[r * 32 + k] = ssum;
        }
        __syncthreads();

        {
            const float wi = wfull[w * 32 + lane];
            int rank = 0;
#pragma unroll
            for (int j = 0; j < 32; j++) {
                const float wj = __shfl_sync(0xffffffffu, wi, j);
                rank += (wj > wi) || (wj == wi && j < lane);
            }
            wmaskT[(n0 + w) * 32 + lane] = (rank < dynK) ? wi : 0.f;
        }
        __syncthreads();
    }

    {
#pragma unroll
        for (int t = 0; t < 4; t++) {
            const int idx = tid + t * 256;
            const int r = idx >> 5, c = idx & 31;
            const float v = wmaskT[r * 32 + c];
            const __half m1 = __float2half_rn(v);
            const __half m2 = __float2half_rn(v - __half2float(m1));
            const uint32_t off = SWZ((uint32_t)(r * 128 + c * 2));
            *(__half*)(wmsm + off)        = m1;
            *(__half*)(wmsm + 4096 + off) = m2;
        }
    }
    __syncthreads();

    const int g = lane >> 3, rw = lane & 7;
    const int mt = w & 1;
    const int pnl = w >> 1;

    float ua[4][2][4];
#pragma unroll
    for (int ntt = 0; ntt < 4; ntt++)
#pragma unroll
        for (int n8 = 0; n8 < 2; n8++)
#pragma unroll
            for (int i = 0; i < 4; i++) ua[ntt][n8][i] = 0.f;

#pragma unroll
    for (int ks = 0; ks < 2; ks++) {
        const int arow = mt * 16 + ((g & 1) << 3) + rw;
        const int acol = ks * 16 + ((g >> 1) << 3);
        const uint32_t ao = SWZ((uint32_t)(arow * 128 + acol * 2));
        uint32_t am1[4], am2[4];
        ldsm4(am1, u_wmsm + ao);
        ldsm4(am2, u_wmsm + 4096 + ao);

        const int trow = ks * 16 + (lane & 7) + ((lane >> 3) & 1) * 8;
        const int tcolb = ((lane >> 4) & 1) * 8;
#pragma unroll
        for (int ntt = 0; ntt < 4; ntt++) {
            const uint32_t bo = pnl * 4096 + SWZ((uint32_t)(trow * 128 + (ntt * 16 + tcolb) * 2));
            uint32_t bi1[4], bi2[4];
            ldsm4t(bi1, u_ism + bo);
            ldsm4t(bi2, u_ism + 16384 + bo);
#pragma unroll
            for (int n8 = 0; n8 < 2; n8++) {
                float* c = ua[ntt][n8];
                mma16816(c, am1, bi1[n8 * 2], bi1[n8 * 2 + 1]);
                mma16816(c, am1, bi2[n8 * 2], bi2[n8 * 2 + 1]);
                mma16816(c, am2, bi1[n8 * 2], bi1[n8 * 2 + 1]);
            }
        }
    }

    const int gid = lane >> 2, tig = lane & 3;
    float* Ob = out + (size_t)b * NCAND * DIM + (size_t)nbase * DIM;
#pragma unroll
    for (int ntt = 0; ntt < 4; ntt++) {
#pragma unroll
        for (int n8 = 0; n8 < 2; n8++) {
            const int d = pnl * 64 + ntt * 16 + n8 * 8 + tig * 2;
            const int r0 = mt * 16 + gid;
            *(float2*)&Ob[(size_t)r0 * 256 + d]       = make_float2(ua[ntt][n8][0], ua[ntt][n8][1]);
            *(float2*)&Ob[(size_t)(r0 + 8) * 256 + d] = make_float2(ua[ntt][n8][2], ua[ntt][n8][3]);
        }
    }
}

// ---------------------------------------------------------------------------
extern "C" void kernel_launch(void* const* d_in, const int* in_sizes, int n_in,
                              void* d_out, int out_size) {
    (void)in_sizes; (void)n_in; (void)out_size;
    const float* hist  = (const float*)d_in[0];
    const float* cand  = (const float*)d_in[2];
    const int*   numI  = (const int*)d_in[3];
    const int*   catC  = (const int*)d_in[4];
    const float* W     = (const float*)d_in[5];
    const float* codes = (const float*)d_in[6];
    float* out = (float*)d_out;

    static bool attr_set = false;
    if (!attr_set) {
        cudaFuncSetAttribute(k1f, cudaFuncAttributeMaxDynamicSharedMemorySize, K1_DYN);
        cudaFuncSetAttribute(k4_kernel, cudaFuncAttributeMaxDynamicSharedMemorySize, K4_SMEM);
        attr_set = true;
    }

    kw_split<<<256, 256>>>(W);
    kc_split<<<32, 256>>>(codes);
    k1f<<<400, 256, K1_DYN>>>(hist);
    k2f<<<BSZ, 128>>>(hist, numI);
    k4_kernel<<<2 * BSZ, 256, K4_SMEM>>>(cand, catC, out);
}